// round 2
// baseline (speedup 1.0000x reference)
#include <cuda_runtime.h>
#include <math.h>
#include <float.h>

// Problem constants
#define B_    2
#define S_    2048
#define BS_   4096
#define V_    50257
#define N_    512
#define NM1_  511
#define NZ_   8
#define CH_   (BS_/NZ_)   // 512 samples per z-slice

#define SCORE_OFF  ((size_t)BS_ * (size_t)V_)                 // 205,852,672
#define MEANDT_OFF (SCORE_OFF + (size_t)BS_ * (size_t)S_)     // +8,388,608

// ----------------------------- device scratch -----------------------------
__device__ float g_rv[BS_];
__device__ float g_k1[BS_];
__device__ float g_tgt[BS_];
__device__ float g_r[BS_];
__device__ float g_c[BS_];
__device__ int   g_kidx[BS_];
__device__ int   g_list[BS_];

__device__ float g_thresh[N_];
__device__ float g_sw[N_];
__device__ float g_sb[N_];
__device__ float g_ss[N_];
__device__ int   g_invperm[N_];

__device__ int g_cnt[N_ + 1];
__device__ int g_off[N_ + 1];
__device__ int g_pos[N_ + 1];

__device__ float g_Wp[(size_t)N_ * V_];  // row j<511: w_out[:, perm(j)+1]; row 511: w_out[:,0]
__device__ float g_A [(size_t)N_ * V_];
__device__ float g_D [(size_t)N_ * V_];

// ----------------------------- helpers -----------------------------
__device__ __forceinline__ float blockReduceSum(float v, float* sh) {
    #pragma unroll
    for (int o = 16; o > 0; o >>= 1) v += __shfl_down_sync(0xffffffffu, v, o);
    int lane = threadIdx.x & 31;
    int w    = threadIdx.x >> 5;
    if (lane == 0) sh[w] = v;
    __syncthreads();
    if (w == 0) {
        v = (lane < (int)(blockDim.x >> 5)) ? sh[lane] : 0.f;
        #pragma unroll
        for (int o = 16; o > 0; o >>= 1) v += __shfl_down_sync(0xffffffffu, v, o);
        if (lane == 0) sh[0] = v;
    }
    __syncthreads();
    float r = sh[0];
    __syncthreads();
    return r;
}

__device__ __forceinline__ float clipf(float x, float lo, float hi) {
    return fminf(fmaxf(x, lo), hi);
}

// ----------------------------- K0: embed + mean(dt) -----------------------------
__global__ void k_embed(const int* __restrict__ x, const float* __restrict__ dt,
                        const float* __restrict__ r0, float* __restrict__ out,
                        size_t out_size) {
    int gid = blockIdx.x * blockDim.x + threadIdx.x;
    if (gid < BS_) {
        float r = r0[x[gid]];
        g_rv[gid] = r / fmaxf(fabsf(r), 1e-12f);
    }
    if (gid == 0 && out_size > MEANDT_OFF) {
        float d0 = clipf(dt[0], 0.f, 1.f);
        float d1 = clipf(dt[1], 0.f, 1.f);
        out[MEANDT_OFF] = 0.5f * (d0 + d1);
    }
}

// ----------------------------- K1: score1 stats + k1 -----------------------------
__global__ void k_step1(const float* __restrict__ dt) {
    __shared__ float srow[S_];
    __shared__ float sred[32];
    int gid = blockIdx.x;
    int b = gid >> 11;
    int i = gid & (S_ - 1);

    for (int j = threadIdx.x; j < S_; j += blockDim.x) srow[j] = g_rv[b * S_ + j];
    __syncthreads();
    float ri = srow[i];

    float s1 = 0.f, s2 = 0.f;
    for (int j = threadIdx.x; j < S_; j += blockDim.x) {
        float d = fabsf(ri - srow[j]);
        s1 += d;
        s2 += d * d;
    }
    s1 = blockReduceSum(s1, sred);
    s2 = blockReduceSum(s2, sred);

    float mean = s1 * (1.f / (float)S_);
    float ssq  = fmaxf(s2 - s1 * mean, 0.f);
    float var  = ssq * (1.f / (float)(S_ - 1));
    float thr  = fmaxf(mean + 2.f * sqrtf(var), 1e-12f);
    float inv  = 1.f / thr;

    float acc = 0.f;
    for (int j = threadIdx.x; j < i; j += blockDim.x) {
        float d = fabsf(ri - srow[j]);
        if (d <= thr) acc += (1.f - d * inv) * srow[j];
    }
    acc = blockReduceSum(acc, sred);

    if (threadIdx.x == 0) {
        float dtc = clipf(dt[b], 0.f, 1.f);
        float k1  = clipf(dtc * acc, -1.f, 1.f);
        g_k1[gid]  = k1;
        g_tgt[gid] = ri + k1;
    }
}

// ----------------------------- K2: score2 + outputs -----------------------------
__global__ void k_step2(const float* __restrict__ dt, float* __restrict__ out,
                        int write_score) {
    __shared__ float srow[S_];
    __shared__ float sred[32];
    int gid = blockIdx.x;
    int b = gid >> 11;
    int i = gid & (S_ - 1);

    for (int j = threadIdx.x; j < S_; j += blockDim.x) srow[j] = g_tgt[b * S_ + j];
    __syncthreads();
    float ti = srow[i];

    float s1 = 0.f, s2 = 0.f;
    for (int j = threadIdx.x; j < S_; j += blockDim.x) {
        float d = fabsf(ti - srow[j]);
        s1 += d;
        s2 += d * d;
    }
    s1 = blockReduceSum(s1, sred);
    s2 = blockReduceSum(s2, sred);

    float mean = s1 * (1.f / (float)S_);
    float ssq  = fmaxf(s2 - s1 * mean, 0.f);
    float var  = ssq * (1.f / (float)(S_ - 1));
    float thr  = fmaxf(mean + 2.f * sqrtf(var), 1e-12f);
    float inv  = 1.f / thr;

    float acc = 0.f, accs = 0.f;
    size_t rowoff = SCORE_OFF + (size_t)gid * S_;
    for (int j = threadIdx.x; j < S_; j += blockDim.x) {
        float d  = fabsf(ti - srow[j]);
        float sc = (j < i && d <= thr) ? (1.f - d * inv) : 0.f;
        if (write_score) out[rowoff + j] = sc;
        acc  += sc * srow[j];
        accs += sc;
    }
    acc  = blockReduceSum(acc, sred);
    accs = blockReduceSum(accs, sred);

    if (threadIdx.x == 0) {
        float dtc = clipf(dt[b], 0.f, 1.f);
        float k2  = clipf(dtc * acc, -1.f, 1.f);
        float z   = g_rv[gid] + 0.5f * (g_k1[gid] + k2);
        g_r[gid]  = z / fmaxf(fabsf(z), 1e-12f);
        g_c[gid]  = clipf(accs * (1.f / (float)S_), 0.f, 1.f);
    }
}

// ----------------------------- K3: thresholds + bitonic sort + init -----------------------------
// Sentinel keys: real breakpoints are provably in (0,1).
//   - real unit that never clips on c in [0,1]: key = 2.0 (never counted: c <= 1 < 2)
//   - dummy slot (index 511):                  key = 3.0 (unique max -> stays at
//     sorted position 511 under strict comparisons, so row 511 of g_Wp is
//     exclusively w_out[:,0])
__global__ void k_sort(const float* __restrict__ w_diff, const float* __restrict__ b_diff) {
    __shared__ float skey[N_];
    __shared__ int   sval[N_];
    int tid = threadIdx.x;

    float t = 3.0f;                 // dummy sentinel (unique max)
    if (tid < NM1_) {
        float w = w_diff[tid], bb = b_diff[tid];
        t = 2.0f;                   // "never clips" sentinel
        if (w > 0.f && (w + bb) > 1.f)        t = (1.f - bb) / w;
        else if (w < 0.f && (w + bb) < -1.f)  t = (-1.f - bb) / w;
    }
    skey[tid] = t;
    sval[tid] = tid;
    __syncthreads();

    for (int ksz = 2; ksz <= N_; ksz <<= 1) {
        for (int jsz = ksz >> 1; jsz > 0; jsz >>= 1) {
            int ixj = tid ^ jsz;
            if (ixj > tid) {
                bool up = ((tid & ksz) == 0);
                float a = skey[tid], c = skey[ixj];
                bool sw = up ? (a > c) : (a < c);
                if (sw) {
                    skey[tid] = c; skey[ixj] = a;
                    int tmp = sval[tid]; sval[tid] = sval[ixj]; sval[ixj] = tmp;
                }
            }
            __syncthreads();
        }
    }

    int n = sval[tid];
    float key = skey[tid];
    g_thresh[tid] = key;
    if (n < NM1_) {
        float w = w_diff[n], bb = b_diff[n];
        g_sw[tid] = w;
        g_sb[tid] = bb;
        g_ss[tid] = (key >= 2.0f) ? 0.f : (w > 0.f ? 1.f : -1.f);
        g_invperm[n] = tid;
    } else {
        g_sw[tid] = 0.f; g_sb[tid] = 0.f; g_ss[tid] = 0.f;
    }
    g_cnt[tid] = 0;
    if (tid == 0) g_cnt[N_] = 0;
}

// ----------------------------- K4: transpose + permute w_out -> g_Wp -----------------------------
__global__ void k_transpose(const float* __restrict__ w_out) {
    __shared__ float tile[32][33];
    int t0 = blockIdx.x * 32;
    int c0 = blockIdx.y * 32;
    int tx = threadIdx.x, ty = threadIdx.y;

    #pragma unroll
    for (int r = 0; r < 32; r += 8) {
        int t = t0 + ty + r;
        int c = c0 + tx;
        tile[ty + r][tx] = (t < V_) ? w_out[(size_t)t * N_ + c] : 0.f;
    }
    __syncthreads();

    #pragma unroll
    for (int r = 0; r < 32; r += 8) {
        int c = c0 + ty + r;      // source column
        int t = t0 + tx;
        int dest = (c == 0) ? NM1_ : g_invperm[c - 1];
        if (t < V_) g_Wp[(size_t)dest * V_ + t] = tile[tx][ty + r];
    }
}

// ----------------------------- K5: build suffix tables A_k, D_k -----------------------------
__global__ void k_tables(const float* __restrict__ b_out) {
    __shared__ float sw[N_], sb[N_], ss[N_];
    for (int j = threadIdx.x; j < N_; j += blockDim.x) {
        sw[j] = g_sw[j]; sb[j] = g_sb[j]; ss[j] = g_ss[j];
    }
    __syncthreads();

    int t = blockIdx.x * blockDim.x + threadIdx.x;
    if (t >= V_) return;

    float a = 0.f, dl = 0.f;
    for (int j = 0; j < NM1_; j++) {
        float w = g_Wp[(size_t)j * V_ + t];
        a  = fmaf(w, sw[j], a);
        dl = fmaf(w, sb[j], dl);
    }
    float dc = 0.f;
    float bo = b_out[t];
    for (int k = 0; k < N_; k++) {
        g_A[(size_t)k * V_ + t] = a;
        g_D[(size_t)k * V_ + t] = dl + dc + bo;
        if (k < NM1_) {
            float w = g_Wp[(size_t)k * V_ + t];
            a  -= w * sw[k];
            dl -= w * sb[k];
            dc += w * ss[k];
        }
    }
}

// ----------------------------- K6: per-sample k index + histogram -----------------------------
__global__ void k_kidx() {
    int gid = blockIdx.x * blockDim.x + threadIdx.x;
    if (gid >= BS_) return;
    float c = g_c[gid];
    int lo = 0, hi = N_;
    while (lo < hi) {
        int mid = (lo + hi) >> 1;
        if (g_thresh[mid] <= c) lo = mid + 1; else hi = mid;
    }
    g_kidx[gid] = lo;
    atomicAdd(&g_cnt[lo], 1);
}

// ----------------------------- K7: prefix sum (tiny, single thread) -----------------------------
__global__ void k_prefix() {
    int off = 0;
    for (int k = 0; k <= N_; k++) {
        g_off[k] = off;
        g_pos[k] = off;
        off += g_cnt[k];
    }
}

// ----------------------------- K8: scatter samples into k-sorted list -----------------------------
__global__ void k_scatter() {
    int gid = blockIdx.x * blockDim.x + threadIdx.x;
    if (gid >= BS_) return;
    int p = atomicAdd(&g_pos[g_kidx[gid]], 1);
    g_list[p] = gid;
}

// ----------------------------- K9: logits -----------------------------
__global__ void k_logits(float* __restrict__ out) {
    __shared__ int   slist[CH_];
    __shared__ int   sk[CH_];
    __shared__ float sr[CH_];
    __shared__ float sc[CH_];

    int t = blockIdx.x * blockDim.x + threadIdx.x;
    bool valid = (t < V_);
    int lo = blockIdx.y * CH_;

    for (int p = threadIdx.x; p < CH_; p += blockDim.x) {
        int sid   = g_list[lo + p];
        slist[p]  = sid;
        sk[p]     = g_kidx[sid];
        sr[p]     = g_r[sid];
        sc[p]     = g_c[sid];
    }
    __syncthreads();

    float w0 = valid ? g_Wp[(size_t)NM1_ * V_ + t] : 0.f;
    int   kcur = -1;
    float a = 0.f, dd = 0.f;

    for (int p = 0; p < CH_; p++) {
        int k = sk[p];
        if (k != kcur) {
            if (valid) {
                a  = g_A[(size_t)k * V_ + t];
                dd = g_D[(size_t)k * V_ + t];
            }
            kcur = k;
        }
        float v = fmaf(sr[p], w0, fmaf(sc[p], a, dd));
        v = fminf(fmaxf(v, -2.f), 2.f);
        if (valid) out[(size_t)slist[p] * V_ + t] = v;
    }
}

// ----------------------------- launch -----------------------------
extern "C" void kernel_launch(void* const* d_in, const int* in_sizes, int n_in,
                              void* d_out, int out_size) {
    const int*   x      = (const int*)  d_in[0];
    const float* dt     = (const float*)d_in[1];
    const float* r0     = (const float*)d_in[2];
    const float* w_diff = (const float*)d_in[3];
    const float* b_diff = (const float*)d_in[4];
    const float* w_out  = (const float*)d_in[5];
    const float* b_out  = (const float*)d_in[6];
    float* out = (float*)d_out;
    size_t osz = (size_t)out_size;

    int write_score = (osz >= SCORE_OFF + (size_t)BS_ * S_) ? 1 : 0;

    k_embed<<<(BS_ + 255) / 256, 256>>>(x, dt, r0, out, osz);
    k_step1<<<BS_, 256>>>(dt);
    k_step2<<<BS_, 256>>>(dt, out, write_score);
    k_sort<<<1, N_>>>(w_diff, b_diff);

    dim3 tb(32, 8);
    dim3 tg((V_ + 31) / 32, N_ / 32);
    k_transpose<<<tg, tb>>>(w_out);

    k_tables<<<(V_ + 255) / 256, 256>>>(b_out);
    k_kidx<<<(BS_ + 255) / 256, 256>>>();
    k_prefix<<<1, 1>>>();
    k_scatter<<<(BS_ + 255) / 256, 256>>>();

    dim3 lg((V_ + 255) / 256, NZ_);
    k_logits<<<lg, 256>>>(out);
}

// round 3
// speedup vs baseline: 1.0588x; 1.0588x over previous
#include <cuda_runtime.h>
#include <math.h>
#include <float.h>

// Problem constants
#define B_    2
#define S_    2048
#define BS_   4096
#define V_    50257
#define V4_   50260          // V_ padded to multiple of 4 (row stride for our tables)
#define N_    512
#define NM1_  511
#define NZ2_  16
#define CH2_  (BS_/NZ2_)     // 256 samples per z-slice
#define SEG_  8
#define SEGW_ 64             // 512 = 8 * 64

#define SCORE_OFF  ((size_t)BS_ * (size_t)V_)
#define MEANDT_OFF (SCORE_OFF + (size_t)BS_ * (size_t)S_)

// ----------------------------- device scratch -----------------------------
__device__ float g_rv[BS_];
__device__ float g_k1[BS_];
__device__ float g_tgt[BS_];
__device__ float g_r[BS_];
__device__ float g_c[BS_];
__device__ int   g_list[BS_];
__device__ int   g_krank[BS_];

__device__ float g_sw[N_];
__device__ float g_sb[N_];
__device__ float g_ss[N_];
__device__ int   g_invperm[N_];
__device__ int   g_rank[N_ + 1];

__device__ __align__(16) float g_Wp[(size_t)N_ * V4_];   // row j<511: permuted w_out col; row 511: w_out[:,0]
__device__ __align__(16) float g_A [(size_t)N_ * V4_];   // compacted suffix tables (used slots only)
__device__ __align__(16) float g_D [(size_t)N_ * V4_];
__device__ __align__(16) float g_segA[(size_t)SEG_ * V4_];
__device__ __align__(16) float g_segB[(size_t)SEG_ * V4_];
__device__ __align__(16) float g_segC[(size_t)SEG_ * V4_];

// ----------------------------- helpers -----------------------------
__device__ __forceinline__ float blockReduceSum(float v, float* sh) {
    #pragma unroll
    for (int o = 16; o > 0; o >>= 1) v += __shfl_down_sync(0xffffffffu, v, o);
    int lane = threadIdx.x & 31;
    int w    = threadIdx.x >> 5;
    if (lane == 0) sh[w] = v;
    __syncthreads();
    if (w == 0) {
        v = (lane < (int)(blockDim.x >> 5)) ? sh[lane] : 0.f;
        #pragma unroll
        for (int o = 16; o > 0; o >>= 1) v += __shfl_down_sync(0xffffffffu, v, o);
        if (lane == 0) sh[0] = v;
    }
    __syncthreads();
    float r = sh[0];
    __syncthreads();
    return r;
}

__device__ __forceinline__ float clipf(float x, float lo, float hi) {
    return fminf(fmaxf(x, lo), hi);
}

// ----------------------------- K0: embed + mean(dt) -----------------------------
__global__ void k_embed(const int* __restrict__ x, const float* __restrict__ dt,
                        const float* __restrict__ r0, float* __restrict__ out,
                        size_t out_size) {
    int gid = blockIdx.x * blockDim.x + threadIdx.x;
    if (gid < BS_) {
        float r = r0[x[gid]];
        g_rv[gid] = r / fmaxf(fabsf(r), 1e-12f);
    }
    if (gid == 0 && out_size > MEANDT_OFF) {
        float d0 = clipf(dt[0], 0.f, 1.f);
        float d1 = clipf(dt[1], 0.f, 1.f);
        out[MEANDT_OFF] = 0.5f * (d0 + d1);
    }
}

// ----------------------------- K1: score1 stats + k1 -----------------------------
__global__ void k_step1(const float* __restrict__ dt) {
    __shared__ float srow[S_];
    __shared__ float sred[32];
    int gid = blockIdx.x;
    int b = gid >> 11;
    int i = gid & (S_ - 1);

    for (int j = threadIdx.x; j < S_; j += blockDim.x) srow[j] = g_rv[b * S_ + j];
    __syncthreads();
    float ri = srow[i];

    float s1 = 0.f, s2 = 0.f;
    for (int j = threadIdx.x; j < S_; j += blockDim.x) {
        float d = fabsf(ri - srow[j]);
        s1 += d;
        s2 += d * d;
    }
    s1 = blockReduceSum(s1, sred);
    s2 = blockReduceSum(s2, sred);

    float mean = s1 * (1.f / (float)S_);
    float ssq  = fmaxf(s2 - s1 * mean, 0.f);
    float var  = ssq * (1.f / (float)(S_ - 1));
    float thr  = fmaxf(mean + 2.f * sqrtf(var), 1e-12f);
    float inv  = 1.f / thr;

    float acc = 0.f;
    for (int j = threadIdx.x; j < i; j += blockDim.x) {
        float d = fabsf(ri - srow[j]);
        if (d <= thr) acc += (1.f - d * inv) * srow[j];
    }
    acc = blockReduceSum(acc, sred);

    if (threadIdx.x == 0) {
        float dtc = clipf(dt[b], 0.f, 1.f);
        float k1  = clipf(dtc * acc, -1.f, 1.f);
        g_k1[gid]  = k1;
        g_tgt[gid] = ri + k1;
    }
}

// ----------------------------- K2: score2 + outputs -----------------------------
__global__ void k_step2(const float* __restrict__ dt, float* __restrict__ out,
                        int write_score) {
    __shared__ float srow[S_];
    __shared__ float sred[32];
    int gid = blockIdx.x;
    int b = gid >> 11;
    int i = gid & (S_ - 1);

    for (int j = threadIdx.x; j < S_; j += blockDim.x) srow[j] = g_tgt[b * S_ + j];
    __syncthreads();
    float ti = srow[i];

    float s1 = 0.f, s2 = 0.f;
    for (int j = threadIdx.x; j < S_; j += blockDim.x) {
        float d = fabsf(ti - srow[j]);
        s1 += d;
        s2 += d * d;
    }
    s1 = blockReduceSum(s1, sred);
    s2 = blockReduceSum(s2, sred);

    float mean = s1 * (1.f / (float)S_);
    float ssq  = fmaxf(s2 - s1 * mean, 0.f);
    float var  = ssq * (1.f / (float)(S_ - 1));
    float thr  = fmaxf(mean + 2.f * sqrtf(var), 1e-12f);
    float inv  = 1.f / thr;

    float acc = 0.f, accs = 0.f;
    size_t rowoff = SCORE_OFF + (size_t)gid * S_;
    for (int j = threadIdx.x; j < S_; j += blockDim.x) {
        float d  = fabsf(ti - srow[j]);
        float sc = (j < i && d <= thr) ? (1.f - d * inv) : 0.f;
        if (write_score) out[rowoff + j] = sc;
        acc  += sc * srow[j];
        accs += sc;
    }
    acc  = blockReduceSum(acc, sred);
    accs = blockReduceSum(accs, sred);

    if (threadIdx.x == 0) {
        float dtc = clipf(dt[b], 0.f, 1.f);
        float k2  = clipf(dtc * acc, -1.f, 1.f);
        float z   = g_rv[gid] + 0.5f * (g_k1[gid] + k2);
        g_r[gid]  = z / fmaxf(fabsf(z), 1e-12f);
        g_c[gid]  = clipf(accs * (1.f / (float)S_), 0.f, 1.f);
    }
}

// ----------------------------- K3: meta (sort + kidx + rank + scatter) -----------------------------
// Sentinels: real breakpoints in (0,1); "never clips" = 2.0; dummy slot 511 = 3.0
// (unique max -> pinned at sorted position 511 under strict comparisons).
__global__ void __launch_bounds__(512) k_meta(const float* __restrict__ w_diff,
                                              const float* __restrict__ b_diff) {
    __shared__ float skey[N_];
    __shared__ int   sval[N_];
    __shared__ int   cnt[N_ + 1];
    __shared__ int   pos[N_ + 1];
    __shared__ int   rnk[N_ + 1];
    int tid = threadIdx.x;

    float t = 3.0f;
    if (tid < NM1_) {
        float w = w_diff[tid], bb = b_diff[tid];
        t = 2.0f;
        if (w > 0.f && (w + bb) > 1.f)        t = (1.f - bb) / w;
        else if (w < 0.f && (w + bb) < -1.f)  t = (-1.f - bb) / w;
    }
    skey[tid] = t;
    sval[tid] = tid;
    __syncthreads();

    for (int ksz = 2; ksz <= N_; ksz <<= 1) {
        for (int jsz = ksz >> 1; jsz > 0; jsz >>= 1) {
            int ixj = tid ^ jsz;
            if (ixj > tid) {
                bool up = ((tid & ksz) == 0);
                float a = skey[tid], c = skey[ixj];
                bool sw = up ? (a > c) : (a < c);
                if (sw) {
                    skey[tid] = c; skey[ixj] = a;
                    int tmp = sval[tid]; sval[tid] = sval[ixj]; sval[ixj] = tmp;
                }
            }
            __syncthreads();
        }
    }

    int n = sval[tid];
    float key = skey[tid];
    if (n < NM1_) {
        float w = w_diff[n], bb = b_diff[n];
        g_sw[tid] = w;
        g_sb[tid] = bb;
        g_ss[tid] = (key >= 2.0f) ? 0.f : (w > 0.f ? 1.f : -1.f);
        g_invperm[n] = tid;
    } else {
        g_sw[tid] = 0.f; g_sb[tid] = 0.f; g_ss[tid] = 0.f;
    }
    cnt[tid] = 0;
    if (tid == 0) cnt[N_] = 0;
    __syncthreads();

    // per-sample bucket (kidx = #keys <= c), histogram
    int kx[BS_ / 512];
    #pragma unroll
    for (int q = 0; q < BS_ / 512; q++) {
        int sid = q * 512 + tid;
        float c = g_c[sid];
        int lo = 0, hi = N_;
        while (lo < hi) {
            int mid = (lo + hi) >> 1;
            if (skey[mid] <= c) lo = mid + 1; else hi = mid;
        }
        kx[q] = lo;
        atomicAdd(&cnt[lo], 1);
    }
    __syncthreads();

    if (tid == 0) {
        int off = 0, r = 0;
        for (int k = 0; k <= N_; k++) {
            pos[k] = off;
            off += cnt[k];
            rnk[k] = (cnt[k] > 0) ? r++ : -1;
        }
    }
    __syncthreads();

    g_rank[tid] = rnk[tid];
    if (tid == 0) g_rank[N_] = rnk[N_];

    #pragma unroll
    for (int q = 0; q < BS_ / 512; q++) {
        int sid = q * 512 + tid;
        int p = atomicAdd(&pos[kx[q]], 1);
        g_list[p] = sid;
        g_krank[sid] = rnk[kx[q]];
    }
}

// ----------------------------- K4: transpose + permute w_out -> g_Wp -----------------------------
__global__ void k_transpose(const float* __restrict__ w_out) {
    __shared__ float tile[32][33];
    int t0 = blockIdx.x * 32;
    int c0 = blockIdx.y * 32;
    int tx = threadIdx.x, ty = threadIdx.y;

    #pragma unroll
    for (int r = 0; r < 32; r += 8) {
        int t = t0 + ty + r;
        int c = c0 + tx;
        tile[ty + r][tx] = (t < V_) ? w_out[(size_t)t * N_ + c] : 0.f;
    }
    __syncthreads();

    #pragma unroll
    for (int r = 0; r < 32; r += 8) {
        int c = c0 + ty + r;      // source column of w_out
        int t = t0 + tx;
        int dest = (c == 0) ? NM1_ : g_invperm[c - 1];
        if (t < V4_) g_Wp[(size_t)dest * V4_ + t] = (t < V_) ? tile[tx][ty + r] : 0.f;
    }
}

// ----------------------------- K5: per-segment partial sums -----------------------------
__global__ void __launch_bounds__(256) k_tabsum() {
    __shared__ float sw[SEGW_], sb[SEGW_], ss[SEGW_];
    int s = blockIdx.y;
    int k0 = s * SEGW_;
    if (threadIdx.x < SEGW_) {
        int k = k0 + threadIdx.x;
        bool ok = (k < NM1_);
        sw[threadIdx.x] = ok ? g_sw[k] : 0.f;
        sb[threadIdx.x] = ok ? g_sb[k] : 0.f;
        ss[threadIdx.x] = ok ? g_ss[k] : 0.f;
    }
    __syncthreads();

    int t = blockIdx.x * 256 + threadIdx.x;
    if (t >= V4_) return;

    int kn = NM1_ - k0; if (kn > SEGW_) kn = SEGW_;
    const float* wp = g_Wp + (size_t)k0 * V4_ + t;
    float pa = 0.f, pb = 0.f, pc = 0.f;
    #pragma unroll 8
    for (int i = 0; i < kn; i++) {
        float w = wp[(size_t)i * V4_];
        pa = fmaf(w, sw[i], pa);
        pb = fmaf(w, sb[i], pb);
        pc = fmaf(w, ss[i], pc);
    }
    g_segA[(size_t)s * V4_ + t] = pa;
    g_segB[(size_t)s * V4_ + t] = pb;
    g_segC[(size_t)s * V4_ + t] = pc;
}

// ----------------------------- K6: write compacted suffix tables A/D at used slots -----------------------------
__global__ void __launch_bounds__(256) k_tables2(const float* __restrict__ b_out) {
    __shared__ float sw[SEGW_], sb[SEGW_], ss[SEGW_];
    __shared__ int   srk[SEGW_];
    int s = blockIdx.y;
    int k0 = s * SEGW_;
    if (threadIdx.x < SEGW_) {
        int k = k0 + threadIdx.x;
        bool ok = (k < NM1_);
        sw[threadIdx.x] = ok ? g_sw[k] : 0.f;
        sb[threadIdx.x] = ok ? g_sb[k] : 0.f;
        ss[threadIdx.x] = ok ? g_ss[k] : 0.f;
        srk[threadIdx.x] = g_rank[k];
    }
    __syncthreads();

    int t = blockIdx.x * 256 + threadIdx.x;
    if (t >= V4_) return;

    float pa = 0.f, pb = 0.f, pc = 0.f, taT = 0.f, tbT = 0.f;
    #pragma unroll
    for (int s2 = 0; s2 < SEG_; s2++) {
        float a2 = g_segA[(size_t)s2 * V4_ + t];
        float b2 = g_segB[(size_t)s2 * V4_ + t];
        float c2 = g_segC[(size_t)s2 * V4_ + t];
        taT += a2; tbT += b2;
        if (s2 < s) { pa += a2; pb += b2; pc += c2; }
    }
    float dbase = tbT + ((t < V_) ? b_out[t] : 0.f);

    const float* wp = g_Wp + (size_t)k0 * V4_ + t;
    #pragma unroll 4
    for (int i = 0; i < SEGW_; i++) {
        int rk = srk[i];
        if (rk >= 0) {
            g_A[(size_t)rk * V4_ + t] = taT - pa;          // sum_{j>=k} w_j*sw_j
            g_D[(size_t)rk * V4_ + t] = dbase - pb + pc;   // sum_{j>=k} w_j*sb_j + sum_{j<k} w_j*ss_j + b_out
        }
        if (k0 + i < NM1_) {
            float w = wp[(size_t)i * V4_];
            pa = fmaf(w, sw[i], pa);
            pb = fmaf(w, sb[i], pb);
            pc = fmaf(w, ss[i], pc);
        }
    }
}

// ----------------------------- K7: logits -----------------------------
__global__ void __launch_bounds__(256) k_logits(float* __restrict__ out) {
    __shared__ int   slist[CH2_];
    __shared__ int   srk[CH2_];
    __shared__ float sr[CH2_];
    __shared__ float sc[CH2_];

    {
        int p = threadIdx.x;
        int sid = g_list[blockIdx.y * CH2_ + p];
        slist[p] = sid;
        srk[p]   = g_krank[sid];
        sr[p]    = g_r[sid];
        sc[p]    = g_c[sid];
    }
    __syncthreads();

    int t0 = blockIdx.x * 1024 + threadIdx.x * 4;
    if (t0 >= V4_) return;

    const float4 w0 = *(const float4*)(g_Wp + (size_t)NM1_ * V4_ + t0);
    bool v0 = (t0     < V_);
    bool v1 = (t0 + 1 < V_);
    bool v2 = (t0 + 2 < V_);
    bool v3 = (t0 + 3 < V_);

    int kcur = -1;
    float4 A = make_float4(0.f, 0.f, 0.f, 0.f);
    float4 D = make_float4(0.f, 0.f, 0.f, 0.f);

    #pragma unroll 4
    for (int p = 0; p < CH2_; p++) {
        int rk = srk[p];
        if (rk != kcur) {
            A = *(const float4*)(g_A + (size_t)rk * V4_ + t0);
            D = *(const float4*)(g_D + (size_t)rk * V4_ + t0);
            kcur = rk;
        }
        float r = sr[p], c = sc[p];
        float x0 = fmaf(r, w0.x, fmaf(c, A.x, D.x));
        float x1 = fmaf(r, w0.y, fmaf(c, A.y, D.y));
        float x2 = fmaf(r, w0.z, fmaf(c, A.z, D.z));
        float x3 = fmaf(r, w0.w, fmaf(c, A.w, D.w));
        x0 = fminf(fmaxf(x0, -2.f), 2.f);
        x1 = fminf(fmaxf(x1, -2.f), 2.f);
        x2 = fminf(fmaxf(x2, -2.f), 2.f);
        x3 = fminf(fmaxf(x3, -2.f), 2.f);
        size_t o = (size_t)slist[p] * V_ + t0;
        if (v0) out[o]     = x0;
        if (v1) out[o + 1] = x1;
        if (v2) out[o + 2] = x2;
        if (v3) out[o + 3] = x3;
    }
}

// ----------------------------- launch -----------------------------
extern "C" void kernel_launch(void* const* d_in, const int* in_sizes, int n_in,
                              void* d_out, int out_size) {
    const int*   x      = (const int*)  d_in[0];
    const float* dt     = (const float*)d_in[1];
    const float* r0     = (const float*)d_in[2];
    const float* w_diff = (const float*)d_in[3];
    const float* b_diff = (const float*)d_in[4];
    const float* w_out  = (const float*)d_in[5];
    const float* b_out  = (const float*)d_in[6];
    float* out = (float*)d_out;
    size_t osz = (size_t)out_size;

    int write_score = (osz >= SCORE_OFF + (size_t)BS_ * S_) ? 1 : 0;

    k_embed<<<(BS_ + 255) / 256, 256>>>(x, dt, r0, out, osz);
    k_step1<<<BS_, 256>>>(dt);
    k_step2<<<BS_, 256>>>(dt, out, write_score);
    k_meta<<<1, 512>>>(w_diff, b_diff);

    dim3 tb(32, 8);
    dim3 tg((V4_ + 31) / 32, N_ / 32);
    k_transpose<<<tg, tb>>>(w_out);

    dim3 sg((V4_ + 255) / 256, SEG_);
    k_tabsum<<<sg, 256>>>();
    k_tables2<<<sg, 256>>>(b_out);

    dim3 lg((V4_ + 1023) / 1024, NZ2_);
    k_logits<<<lg, 256>>>(out);
}